// round 16
// baseline (speedup 1.0000x reference)
#include <cuda_runtime.h>
#include <cuda_fp16.h>
#include <cstdint>
#include <math.h>

// Problem constants
#define BATCH 4
#define H 1024
#define L 8192
#define KD 64
#define NS 4
#define TAPS 512

// Scratch
__device__ float  g_filt[H * TAPS];                      // 2 MB
__device__ __half g_vh[(size_t)BATCH * H * L];           // 64 MB   v[b,h,l] fp16
__device__ __half g_wh[H * H];                           // 2 MB    W fp16

// ===========================================================================
// Helpers
// ===========================================================================
__device__ __forceinline__ void mma16n8k16h(float d[4], const uint32_t a[4],
                                            const uint32_t b0, const uint32_t b1,
                                            const float c[4]) {
    asm("mma.sync.aligned.m16n8k16.row.col.f32.f16.f16.f32 "
        "{%0,%1,%2,%3}, {%4,%5,%6,%7}, {%8,%9}, {%10,%11,%12,%13};"
        : "=f"(d[0]), "=f"(d[1]), "=f"(d[2]), "=f"(d[3])
        : "r"(a[0]), "r"(a[1]), "r"(a[2]), "r"(a[3]),
          "r"(b0), "r"(b1),
          "f"(c[0]), "f"(c[1]), "f"(c[2]), "f"(c[3]));
}

__device__ __forceinline__ void ldsm_x4(uint32_t& r0, uint32_t& r1,
                                        uint32_t& r2, uint32_t& r3, uint32_t addr) {
    asm volatile("ldmatrix.sync.aligned.m8n8.x4.shared.b16 {%0,%1,%2,%3}, [%4];"
                 : "=r"(r0), "=r"(r1), "=r"(r2), "=r"(r3) : "r"(addr));
}
__device__ __forceinline__ void ldsm_x4_t(uint32_t& r0, uint32_t& r1,
                                          uint32_t& r2, uint32_t& r3, uint32_t addr) {
    asm volatile("ldmatrix.sync.aligned.m8n8.x4.trans.shared.b16 {%0,%1,%2,%3}, [%4];"
                 : "=r"(r0), "=r"(r1), "=r"(r2), "=r"(r3) : "r"(addr));
}

__device__ __forceinline__ uint32_t smem_u32(const void* p) {
    uint32_t a;
    asm("{ .reg .u64 t; cvta.to.shared.u64 t, %1; cvt.u32.u64 %0, t; }" : "=r"(a) : "l"(p));
    return a;
}
__device__ __forceinline__ void cp_async16(uint32_t dst, const void* src) {
    asm volatile("cp.async.cg.shared.global [%0], [%1], 16;" :: "r"(dst), "l"(src));
}
__device__ __forceinline__ uint32_t packh2(float a, float b) {
    __half2 p = __floats2half2_rn(a, b);
    return *(uint32_t*)&p;
}

// ===========================================================================
// Kernel 1: build the multi-resolution filter, L2-normalized per head.
// ===========================================================================
__global__ void build_filter_kernel(const float* __restrict__ k0,
                                    const float* __restrict__ k1,
                                    const float* __restrict__ k2,
                                    const float* __restrict__ k3) {
    int h = blockIdx.x;
    int t = threadIdx.x;

    const float* ks[NS] = {k0, k1, k2, k3};
    float acc = 0.0f;
#pragma unroll
    for (int i = 0; i < NS; ++i) {
        int len = KD << i;
        if (t < len) {
            float scale = (float)(1 << i);
            float coord = ((float)t + 0.5f) / scale - 0.5f;
            coord = fminf(fmaxf(coord, 0.0f), (float)(KD - 1));
            int lo = (int)floorf(coord);
            int hi = min(lo + 1, KD - 1);
            float w = coord - (float)lo;
            const float* kp = ks[i] + h * KD;
            float v = kp[lo] * (1.0f - w) + kp[hi] * w;
            acc += v * (float)(1 << (NS - 1 - i));
        }
    }

    __shared__ float red[TAPS];
    red[t] = acc * acc;
    __syncthreads();
#pragma unroll
    for (int s = TAPS / 2; s > 0; s >>= 1) {
        if (t < s) red[t] += red[t + s];
        __syncthreads();
    }
    float inv_norm = rsqrtf(red[0]);
    g_filt[h * TAPS + t] = acc * inv_norm;
}

// ===========================================================================
// Kernel 1b: W -> fp16 copy
// ===========================================================================
__global__ void wprep_kernel(const float* __restrict__ Wm) {
    int i = blockIdx.x * 256 + threadIdx.x;
    g_wh[i] = __float2half_rn(Wm[i]);
}

// ===========================================================================
// Kernel 2: Toeplitz conv (one batch): y = k (*) u + D*u, GeLU -> g_vh
//   grid = H blocks; u_b points at batch b's rows.
// ===========================================================================
#define CUS 36    // u_s row stride in words

__global__ __launch_bounds__(128)
void conv_mma_fp16(const float* __restrict__ u_b, const float* __restrict__ D,
                   int b) {
    __shared__ uint32_t u_s[136 * CUS];
    __shared__ uint32_t kp_s[640];

    int h = blockIdx.x;
    int tid  = threadIdx.x;
    int lane = tid & 31;
    int wid  = tid >> 5;
    int gid = lane >> 2;
    int tig = lane & 3;

    int wm0 = (wid & 1) * 64;
    int wn0 = (wid >> 1) * 32;

    const float* up = u_b + (size_t)h * L;

    for (int j = tid; j < 640; j += 128) {
        int t0 = j - 64, t1 = j - 65;
        float lo = (t0 >= 0 && t0 < TAPS) ? g_filt[h * TAPS + t0] : 0.0f;
        float hi = (t1 >= 0 && t1 < TAPS) ? g_filt[h * TAPS + t1] : 0.0f;
        kp_s[j] = packh2(lo, hi);
    }
    for (int w = tid; w < 256; w += 128)
        u_s[(w >> 5) * CUS + (w & 31)] = 0u;
    for (int j = tid; j < L / 4; j += 128) {
        float4 x = ((const float4*)up)[j];
        int e = 512 + j * 4;
        int row = e >> 6, w = (e & 63) >> 1;
        u_s[row * CUS + w]     = packh2(x.x, x.y);
        u_s[row * CUS + w + 1] = packh2(x.z, x.w);
    }
    __syncthreads();

    float acc[4][4][4];
#pragma unroll
    for (int s = 0; s < 4; ++s)
#pragma unroll
        for (int q = 0; q < 4; ++q)
#pragma unroll
            for (int e = 0; e < 4; ++e) acc[s][q][e] = 0.0f;

#pragma unroll 1
    for (int d = 0; d < 9; ++d) {
        int rbase = wm0 + gid + 8 - d;
        int xbase = 64 + wn0 + gid - 2 * tig + 64 * d;
#pragma unroll
        for (int msi = 0; msi < 4; ++msi) {
            int msw = msi * 8;
            uint32_t a[4][4];
#pragma unroll
            for (int s = 0; s < 4; ++s) {
                int row = rbase + s * 16;
                a[s][0] = u_s[row * CUS + msw + tig];
                a[s][1] = u_s[(row + 8) * CUS + msw + tig];
                a[s][2] = u_s[row * CUS + msw + tig + 4];
                a[s][3] = u_s[(row + 8) * CUS + msw + tig + 4];
            }
            uint32_t b0[4], b1[4];
#pragma unroll
            for (int q = 0; q < 4; ++q) {
                int x = xbase + q * 8 - msi * 16;
                b0[q] = kp_s[x];
                b1[q] = kp_s[x - 8];
            }
#pragma unroll
            for (int s = 0; s < 4; ++s)
#pragma unroll
                for (int q = 0; q < 4; ++q)
                    mma16n8k16h(acc[s][q], a[s], b0[q], b1[q], acc[s][q]);
        }
    }

    float dv = D[h];
    __half* vp = g_vh + ((size_t)b * H + h) * L;
#pragma unroll
    for (int s = 0; s < 4; ++s) {
#pragma unroll
        for (int q = 0; q < 4; ++q) {
            int n = wn0 + q * 8 + 2 * tig;
#pragma unroll
            for (int half = 0; half < 2; ++half) {
                int r = wm0 + s * 16 + gid + half * 8;
                uint32_t uw = u_s[(r + 8) * CUS + (n >> 1)];
                float2 uf = __half22float2(*(__half2*)&uw);
                float x0 = acc[s][q][half * 2 + 0] + dv * uf.x;
                float x1 = acc[s][q][half * 2 + 1] + dv * uf.y;
                float g0 = 0.5f * x0 * (1.0f + erff(x0 * 0.70710678118654752f));
                float g1 = 0.5f * x1 * (1.0f + erff(x1 * 0.70710678118654752f));
                *(__half2*)(vp + r * 64 + n) = __floats2half2_rn(g0, g1);
            }
        }
    }
}

// ===========================================================================
// Kernel 3: fp16 mma GEMM (one batch), BK=64, rolling B buffer.
//   out_b[o,l] = sum_f W[o,f] * v_b[f,l] + bias[o]
// ===========================================================================
#define GBM 128
#define GBN 128
#define GBK 64
#define ABS 144
#define BBS 272
#define A_STAGE_B (GBM * ABS)
#define B_STAGE_B (GBK * BBS)
#define STAGE_B (A_STAGE_B + B_STAGE_B)
#define GSTG 3
#define GEMM_SMEM_BYTES (GSTG * STAGE_B)
#define GNCHUNK (H / GBK)

extern __shared__ uint32_t g_smem[];

__global__ __launch_bounds__(256, 2)
void gemm_mma_fp16(const float* __restrict__ bias, float* __restrict__ out_b,
                   int b) {
    int nb = blockIdx.x * GBN;
    int mb = blockIdx.y * GBM;
    const __half* vh = g_vh + (size_t)b * H * L;

    int tid  = threadIdx.x;
    int lane = tid & 31;
    int wid  = tid >> 5;
    int wm0 = (wid & 3) * 32;
    int wn0 = (wid >> 2) * 64;
    int gid = lane >> 2;
    int tig = lane & 3;

    uint32_t sbase = smem_u32(g_smem);

    int rA = tid >> 3, sA = tid & 7;
    int rB = tid >> 4, sB = tid & 15;
    const __half* Ag = g_wh + (size_t)(mb + rA) * H + sA * 8;
    uint32_t a_dst = (uint32_t)(rA * ABS + sA * 16);
    uint32_t b_dst = (uint32_t)(rB * BBS + sB * 16);

    int l16 = lane & 15, lhi = lane >> 4;
    uint32_t a_off0 = (uint32_t)((wm0 + l16) * ABS + lhi * 16);
    uint32_t a_off1 = a_off0 + 16 * ABS;
    int l8 = lane & 7, lt = lane >> 3;
    uint32_t b_lane = (uint32_t)(((lt & 1) * 8 + l8) * BBS + (lt >> 1) * 16);
    uint32_t b_off[4];
#pragma unroll
    for (int q = 0; q < 4; ++q)
        b_off[q] = b_lane + (uint32_t)((wn0 + q * 16) * 2);

#define ISSUE_CHUNK(c_) do {                                                  \
        int st_ = (c_) % GSTG;                                                \
        uint32_t sa_ = sbase + (uint32_t)(st_ * STAGE_B);                     \
        uint32_t sb_ = sa_ + (uint32_t)A_STAGE_B;                             \
        const __half* ag_ = Ag + (c_) * GBK;                                  \
        const __half* bg_ = vh + (size_t)((c_) * GBK + rB) * L + nb + sB * 8; \
        _Pragma("unroll")                                                     \
        for (int r_ = 0; r_ < 4; ++r_) {                                      \
            cp_async16(sa_ + a_dst + (uint32_t)(r_ * 32 * ABS),               \
                       ag_ + (size_t)(r_ * 32) * H);                          \
            cp_async16(sb_ + b_dst + (uint32_t)(r_ * 16 * BBS),               \
                       bg_ + (size_t)(r_ * 16) * L);                          \
        }                                                                     \
    } while (0)

#pragma unroll
    for (int c = 0; c < GSTG - 1; ++c) {
        ISSUE_CHUNK(c);
        asm volatile("cp.async.commit_group;" ::: "memory");
    }

    float acc[2][8][4];
#pragma unroll
    for (int s = 0; s < 2; ++s)
#pragma unroll
        for (int j = 0; j < 8; ++j)
#pragma unroll
            for (int e = 0; e < 4; ++e) acc[s][j][e] = 0.0f;

#pragma unroll 1
    for (int c = 0; c < GNCHUNK; ++c) {
        asm volatile("cp.async.wait_group %0;" :: "n"(GSTG - 2) : "memory");
        __syncthreads();

        if (c + GSTG - 1 < GNCHUNK) ISSUE_CHUNK(c + GSTG - 1);
        asm volatile("cp.async.commit_group;" ::: "memory");

        uint32_t sa = sbase + (uint32_t)((c % GSTG) * STAGE_B);
        uint32_t sb = sa + (uint32_t)A_STAGE_B;

#pragma unroll
        for (int ks = 0; ks < 4; ++ks) {
            uint32_t a[2][4];
            ldsm_x4(a[0][0], a[0][1], a[0][2], a[0][3], sa + a_off0 + ks * 32);
            ldsm_x4(a[1][0], a[1][1], a[1][2], a[1][3], sa + a_off1 + ks * 32);

            uint32_t kofB = (uint32_t)(ks * 16 * BBS);
            uint32_t c0, c1, c2, c3, n0, n1, n2, n3;
            ldsm_x4_t(c0, c1, c2, c3, sb + b_off[0] + kofB);
#pragma unroll
            for (int q = 0; q < 4; ++q) {
                if (q < 3)
                    ldsm_x4_t(n0, n1, n2, n3, sb + b_off[q + 1] + kofB);
                mma16n8k16h(acc[0][q * 2],     a[0], c0, c1, acc[0][q * 2]);
                mma16n8k16h(acc[1][q * 2],     a[1], c0, c1, acc[1][q * 2]);
                mma16n8k16h(acc[0][q * 2 + 1], a[0], c2, c3, acc[0][q * 2 + 1]);
                mma16n8k16h(acc[1][q * 2 + 1], a[1], c2, c3, acc[1][q * 2 + 1]);
                c0 = n0; c1 = n1; c2 = n2; c3 = n3;
            }
        }
    }

#pragma unroll
    for (int s = 0; s < 2; ++s) {
        int r0 = mb + wm0 + s * 16 + gid;
        int r1 = r0 + 8;
        float bv0 = bias[r0];
        float bv1 = bias[r1];
        float* o0 = out_b + (size_t)r0 * L + nb + wn0 + tig * 2;
        float* o1 = out_b + (size_t)r1 * L + nb + wn0 + tig * 2;
#pragma unroll
        for (int j = 0; j < 8; ++j) {
            *(float2*)(o0 + j * 8) = make_float2(acc[s][j][0] + bv0, acc[s][j][1] + bv0);
            *(float2*)(o1 + j * 8) = make_float2(acc[s][j][2] + bv1, acc[s][j][3] + bv1);
        }
    }
}

// ===========================================================================
// Launch: conv stream (s1) overlapped with GEMM stream (default), per batch.
// ===========================================================================
extern "C" void kernel_launch(void* const* d_in, const int* in_sizes, int n_in,
                              void* d_out, int out_size) {
    const float* u  = (const float*)d_in[0];
    const float* k0 = (const float*)d_in[1];
    const float* k1 = (const float*)d_in[2];
    const float* k2 = (const float*)d_in[3];
    const float* k3 = (const float*)d_in[4];
    const float* D  = (const float*)d_in[5];
    const float* Wm = (const float*)d_in[6];
    const float* b  = (const float*)d_in[7];
    float* out = (float*)d_out;

    // One-time setup on the first (uncaptured) correctness call.
    static cudaStream_t s1 = nullptr;
    static cudaEvent_t evFork;
    static cudaEvent_t evConv[BATCH];
    if (s1 == nullptr) {
        cudaStreamCreateWithFlags(&s1, cudaStreamNonBlocking);
        cudaEventCreateWithFlags(&evFork, cudaEventDisableTiming);
        for (int i = 0; i < BATCH; ++i)
            cudaEventCreateWithFlags(&evConv[i], cudaEventDisableTiming);
        cudaFuncSetAttribute(gemm_mma_fp16,
                             cudaFuncAttributeMaxDynamicSharedMemorySize,
                             GEMM_SMEM_BYTES);
    }

    // Fork s1 from the capture (default) stream.
    cudaEventRecord(evFork, 0);
    cudaStreamWaitEvent(s1, evFork, 0);

    // s1: filter build + per-batch convs.
    build_filter_kernel<<<H, TAPS, 0, s1>>>(k0, k1, k2, k3);
    for (int bb = 0; bb < BATCH; ++bb) {
        conv_mma_fp16<<<H, 128, 0, s1>>>(u + (size_t)bb * H * L, D, bb);
        cudaEventRecord(evConv[bb], s1);
    }

    // default stream: W prep, then per-batch GEMMs gated on conv(b).
    wprep_kernel<<<H * H / 256, 256>>>(Wm);
    dim3 ggrid(L / GBN, H / GBM, 1);
    for (int bb = 0; bb < BATCH; ++bb) {
        cudaStreamWaitEvent(0, evConv[bb], 0);
        gemm_mma_fp16<<<ggrid, 256, GEMM_SMEM_BYTES>>>(
            b, out + (size_t)bb * H * L, bb);
    }
}

// round 17
// speedup vs baseline: 1.0959x; 1.0959x over previous
#include <cuda_runtime.h>
#include <cuda_fp16.h>
#include <cstdint>
#include <math.h>

// Problem constants
#define BATCH 4
#define H 1024
#define L 8192
#define KD 64
#define NS 4
#define TAPS 512

// Scratch
__device__ float  g_filt[H * TAPS];                      // 2 MB
__device__ __half g_vh[(size_t)BATCH * H * L];           // 64 MB   v[b,h,l] fp16
__device__ __half g_wh[H * H];                           // 2 MB    W fp16

// ===========================================================================
// Helpers
// ===========================================================================
__device__ __forceinline__ void mma16n8k16h(float d[4], const uint32_t a[4],
                                            const uint32_t b0, const uint32_t b1,
                                            const float c[4]) {
    asm("mma.sync.aligned.m16n8k16.row.col.f32.f16.f16.f32 "
        "{%0,%1,%2,%3}, {%4,%5,%6,%7}, {%8,%9}, {%10,%11,%12,%13};"
        : "=f"(d[0]), "=f"(d[1]), "=f"(d[2]), "=f"(d[3])
        : "r"(a[0]), "r"(a[1]), "r"(a[2]), "r"(a[3]),
          "r"(b0), "r"(b1),
          "f"(c[0]), "f"(c[1]), "f"(c[2]), "f"(c[3]));
}

__device__ __forceinline__ void ldsm_x4(uint32_t& r0, uint32_t& r1,
                                        uint32_t& r2, uint32_t& r3, uint32_t addr) {
    asm volatile("ldmatrix.sync.aligned.m8n8.x4.shared.b16 {%0,%1,%2,%3}, [%4];"
                 : "=r"(r0), "=r"(r1), "=r"(r2), "=r"(r3) : "r"(addr));
}
__device__ __forceinline__ void ldsm_x4_t(uint32_t& r0, uint32_t& r1,
                                          uint32_t& r2, uint32_t& r3, uint32_t addr) {
    asm volatile("ldmatrix.sync.aligned.m8n8.x4.trans.shared.b16 {%0,%1,%2,%3}, [%4];"
                 : "=r"(r0), "=r"(r1), "=r"(r2), "=r"(r3) : "r"(addr));
}

__device__ __forceinline__ uint32_t smem_u32(const void* p) {
    uint32_t a;
    asm("{ .reg .u64 t; cvta.to.shared.u64 t, %1; cvt.u32.u64 %0, t; }" : "=r"(a) : "l"(p));
    return a;
}
__device__ __forceinline__ void cp_async16(uint32_t dst, const void* src) {
    asm volatile("cp.async.cg.shared.global [%0], [%1], 16;" :: "r"(dst), "l"(src));
}
__device__ __forceinline__ uint32_t packh2(float a, float b) {
    __half2 p = __floats2half2_rn(a, b);
    return *(uint32_t*)&p;
}

// ===========================================================================
// Kernel 1: build the multi-resolution filter, L2-normalized per head.
// ===========================================================================
__global__ void build_filter_kernel(const float* __restrict__ k0,
                                    const float* __restrict__ k1,
                                    const float* __restrict__ k2,
                                    const float* __restrict__ k3) {
    int h = blockIdx.x;
    int t = threadIdx.x;

    const float* ks[NS] = {k0, k1, k2, k3};
    float acc = 0.0f;
#pragma unroll
    for (int i = 0; i < NS; ++i) {
        int len = KD << i;
        if (t < len) {
            float scale = (float)(1 << i);
            float coord = ((float)t + 0.5f) / scale - 0.5f;
            coord = fminf(fmaxf(coord, 0.0f), (float)(KD - 1));
            int lo = (int)floorf(coord);
            int hi = min(lo + 1, KD - 1);
            float w = coord - (float)lo;
            const float* kp = ks[i] + h * KD;
            float v = kp[lo] * (1.0f - w) + kp[hi] * w;
            acc += v * (float)(1 << (NS - 1 - i));
        }
    }

    __shared__ float red[TAPS];
    red[t] = acc * acc;
    __syncthreads();
#pragma unroll
    for (int s = TAPS / 2; s > 0; s >>= 1) {
        if (t < s) red[t] += red[t + s];
        __syncthreads();
    }
    float inv_norm = rsqrtf(red[0]);
    g_filt[h * TAPS + t] = acc * inv_norm;
}

// ===========================================================================
// Kernel 1b: W -> fp16 copy
// ===========================================================================
__global__ void wprep_kernel(const float* __restrict__ Wm) {
    int i = blockIdx.x * 256 + threadIdx.x;
    g_wh[i] = __float2half_rn(Wm[i]);
}

// ===========================================================================
// Kernel 2: Toeplitz conv with fp16 m16n8k16: y = k (*) u + D*u, GeLU -> g_vh
// ===========================================================================
#define CUS 36    // u_s row stride in words

__global__ __launch_bounds__(128)
void conv_mma_fp16(const float* __restrict__ u, const float* __restrict__ D) {
    __shared__ uint32_t u_s[136 * CUS];
    __shared__ uint32_t kp_s[640];

    int bh = blockIdx.x;
    int h  = bh & (H - 1);
    int tid  = threadIdx.x;
    int lane = tid & 31;
    int wid  = tid >> 5;
    int gid = lane >> 2;
    int tig = lane & 3;

    int wm0 = (wid & 1) * 64;
    int wn0 = (wid >> 1) * 32;

    const float* up = u + (size_t)bh * L;

    for (int j = tid; j < 640; j += 128) {
        int t0 = j - 64, t1 = j - 65;
        float lo = (t0 >= 0 && t0 < TAPS) ? g_filt[h * TAPS + t0] : 0.0f;
        float hi = (t1 >= 0 && t1 < TAPS) ? g_filt[h * TAPS + t1] : 0.0f;
        kp_s[j] = packh2(lo, hi);
    }
    for (int w = tid; w < 256; w += 128)
        u_s[(w >> 5) * CUS + (w & 31)] = 0u;
    for (int j = tid; j < L / 4; j += 128) {
        float4 x = ((const float4*)up)[j];
        int e = 512 + j * 4;
        int row = e >> 6, w = (e & 63) >> 1;
        u_s[row * CUS + w]     = packh2(x.x, x.y);
        u_s[row * CUS + w + 1] = packh2(x.z, x.w);
    }
    __syncthreads();

    float acc[4][4][4];
#pragma unroll
    for (int s = 0; s < 4; ++s)
#pragma unroll
        for (int q = 0; q < 4; ++q)
#pragma unroll
            for (int e = 0; e < 4; ++e) acc[s][q][e] = 0.0f;

#pragma unroll 1
    for (int d = 0; d < 9; ++d) {
        int rbase = wm0 + gid + 8 - d;
        int xbase = 64 + wn0 + gid - 2 * tig + 64 * d;
#pragma unroll
        for (int msi = 0; msi < 4; ++msi) {
            int msw = msi * 8;
            uint32_t a[4][4];
#pragma unroll
            for (int s = 0; s < 4; ++s) {
                int row = rbase + s * 16;
                a[s][0] = u_s[row * CUS + msw + tig];
                a[s][1] = u_s[(row + 8) * CUS + msw + tig];
                a[s][2] = u_s[row * CUS + msw + tig + 4];
                a[s][3] = u_s[(row + 8) * CUS + msw + tig + 4];
            }
            uint32_t b0[4], b1[4];
#pragma unroll
            for (int q = 0; q < 4; ++q) {
                int x = xbase + q * 8 - msi * 16;
                b0[q] = kp_s[x];
                b1[q] = kp_s[x - 8];
            }
#pragma unroll
            for (int s = 0; s < 4; ++s)
#pragma unroll
                for (int q = 0; q < 4; ++q)
                    mma16n8k16h(acc[s][q], a[s], b0[q], b1[q], acc[s][q]);
        }
    }

    float dv = D[h];
    __half* vp = g_vh + (size_t)bh * L;
#pragma unroll
    for (int s = 0; s < 4; ++s) {
#pragma unroll
        for (int q = 0; q < 4; ++q) {
            int n = wn0 + q * 8 + 2 * tig;
#pragma unroll
            for (int half = 0; half < 2; ++half) {
                int r = wm0 + s * 16 + gid + half * 8;
                uint32_t uw = u_s[(r + 8) * CUS + (n >> 1)];
                float2 uf = __half22float2(*(__half2*)&uw);
                float x0 = acc[s][q][half * 2 + 0] + dv * uf.x;
                float x1 = acc[s][q][half * 2 + 1] + dv * uf.y;
                float g0 = 0.5f * x0 * (1.0f + erff(x0 * 0.70710678118654752f));
                float g1 = 0.5f * x1 * (1.0f + erff(x1 * 0.70710678118654752f));
                *(__half2*)(vp + r * 64 + n) = __floats2half2_rn(g0, g1);
            }
        }
    }
}

// ===========================================================================
// Kernel 3: fp16 mma GEMM, 64x64 warp tiles (CUTLASS shape), BK=64.
//   out[b,o,l] = sum_f W[o,f] * v[b,f,l] + bias[o]
//   CTA tile 128(M=o) x 128(N=l) x 64(K=f); 4 warps (2M x 2N), warp 64x64.
// ===========================================================================
#define GBM 128
#define GBN 128
#define GBK 64
#define ABS 144                              // A row stride bytes
#define BBS 272                              // B row stride bytes
#define A_STAGE_B (GBM * ABS)                // 18432
#define B_STAGE_B (GBK * BBS)                // 17408
#define STAGE_B (A_STAGE_B + B_STAGE_B)      // 35840
#define GSTG 3
#define GEMM_SMEM_BYTES (GSTG * STAGE_B)     // 107520
#define GNCHUNK (H / GBK)                    // 16

extern __shared__ uint32_t g_smem[];

__global__ __launch_bounds__(128, 2)
void gemm_mma_fp16(const float* __restrict__ bias, float* __restrict__ out) {
    int bz = blockIdx.z;
    int nb = blockIdx.x * GBN;
    int mb = blockIdx.y * GBM;
    const __half* vh = g_vh + (size_t)bz * H * L;

    int tid  = threadIdx.x;
    int lane = tid & 31;
    int wid  = tid >> 5;           // 0..3
    int wm0 = (wid & 1) * 64;      // warp M offset
    int wn0 = (wid >> 1) * 64;     // warp N offset
    int gid = lane >> 2;
    int tig = lane & 3;

    uint32_t sbase = smem_u32(g_smem);

    // cp.async fill mapping (128 threads: 16 x 16B per thread per chunk)
    int rA = tid >> 3, sA = tid & 7;          // A: 16 rows/pass x 8 slots, 8 passes
    int rB = tid >> 4, sB = tid & 15;         // B: 8 rows/pass x 16 slots, 8 passes
    const __half* Ag = g_wh + (size_t)(mb + rA) * H + sA * 8;
    uint32_t a_dst = (uint32_t)(rA * ABS + sA * 16);
    uint32_t b_dst = (uint32_t)(rB * BBS + sB * 16);

    // ldmatrix lane offsets
    int l16 = lane & 15, lhi = lane >> 4;
    uint32_t a_offs[4];
#pragma unroll
    for (int s = 0; s < 4; ++s)
        a_offs[s] = (uint32_t)((wm0 + s * 16 + l16) * ABS + lhi * 16);
    int l8 = lane & 7, lt = lane >> 3;
    uint32_t b_lane = (uint32_t)(((lt & 1) * 8 + l8) * BBS + (lt >> 1) * 16);
    uint32_t b_off[4];
#pragma unroll
    for (int q = 0; q < 4; ++q)
        b_off[q] = b_lane + (uint32_t)((wn0 + q * 16) * 2);

#define ISSUE_CHUNK(c_) do {                                                  \
        int st_ = (c_) % GSTG;                                                \
        uint32_t sa_ = sbase + (uint32_t)(st_ * STAGE_B);                     \
        uint32_t sb_ = sa_ + (uint32_t)A_STAGE_B;                             \
        const __half* ag_ = Ag + (c_) * GBK;                                  \
        const __half* bg_ = vh + (size_t)((c_) * GBK + rB) * L + nb + sB * 8; \
        _Pragma("unroll")                                                     \
        for (int r_ = 0; r_ < 8; ++r_) {                                      \
            cp_async16(sa_ + a_dst + (uint32_t)(r_ * 16 * ABS),               \
                       ag_ + (size_t)(r_ * 16) * H);                          \
            cp_async16(sb_ + b_dst + (uint32_t)(r_ * 8 * BBS),                \
                       bg_ + (size_t)(r_ * 8) * L);                           \
        }                                                                     \
    } while (0)

#pragma unroll
    for (int c = 0; c < GSTG - 1; ++c) {
        ISSUE_CHUNK(c);
        asm volatile("cp.async.commit_group;" ::: "memory");
    }

    float acc[4][8][4];
#pragma unroll
    for (int s = 0; s < 4; ++s)
#pragma unroll
        for (int j = 0; j < 8; ++j)
#pragma unroll
            for (int e = 0; e < 4; ++e) acc[s][j][e] = 0.0f;

#pragma unroll 1
    for (int c = 0; c < GNCHUNK; ++c) {
        asm volatile("cp.async.wait_group %0;" :: "n"(GSTG - 2) : "memory");
        __syncthreads();

        if (c + GSTG - 1 < GNCHUNK) ISSUE_CHUNK(c + GSTG - 1);
        asm volatile("cp.async.commit_group;" ::: "memory");

        uint32_t sa = sbase + (uint32_t)((c % GSTG) * STAGE_B);
        uint32_t sb = sa + (uint32_t)A_STAGE_B;

#pragma unroll
        for (int ks = 0; ks < 4; ++ks) {       // four k16 steps per BK=64
            uint32_t a[4][4];
#pragma unroll
            for (int s = 0; s < 4; ++s)
                ldsm_x4(a[s][0], a[s][1], a[s][2], a[s][3],
                        sa + a_offs[s] + ks * 32);

            uint32_t kofB = (uint32_t)(ks * 16 * BBS);
            uint32_t c0, c1, c2, c3, n0, n1, n2, n3;
            ldsm_x4_t(c0, c1, c2, c3, sb + b_off[0] + kofB);
#pragma unroll
            for (int q = 0; q < 4; ++q) {
                if (q < 3)
                    ldsm_x4_t(n0, n1, n2, n3, sb + b_off[q + 1] + kofB);
#pragma unroll
                for (int s = 0; s < 4; ++s) {
                    mma16n8k16h(acc[s][q * 2],     a[s], c0, c1, acc[s][q * 2]);
                    mma16n8k16h(acc[s][q * 2 + 1], a[s], c2, c3, acc[s][q * 2 + 1]);
                }
                c0 = n0; c1 = n1; c2 = n2; c3 = n3;
            }
        }
    }

    // ---- epilogue ----
#pragma unroll
    for (int s = 0; s < 4; ++s) {
        int r0 = mb + wm0 + s * 16 + gid;
        int r1 = r0 + 8;
        float bv0 = bias[r0];
        float bv1 = bias[r1];
        float* o0 = out + ((size_t)bz * H + r0) * L + nb + wn0 + tig * 2;
        float* o1 = out + ((size_t)bz * H + r1) * L + nb + wn0 + tig * 2;
#pragma unroll
        for (int j = 0; j < 8; ++j) {
            *(float2*)(o0 + j * 8) = make_float2(acc[s][j][0] + bv0, acc[s][j][1] + bv0);
            *(float2*)(o1 + j * 8) = make_float2(acc[s][j][2] + bv1, acc[s][j][3] + bv1);
        }
    }
}

// ===========================================================================
// Launch (monolithic, single stream — R15 structure)
// ===========================================================================
extern "C" void kernel_launch(void* const* d_in, const int* in_sizes, int n_in,
                              void* d_out, int out_size) {
    const float* u  = (const float*)d_in[0];
    const float* k0 = (const float*)d_in[1];
    const float* k1 = (const float*)d_in[2];
    const float* k2 = (const float*)d_in[3];
    const float* k3 = (const float*)d_in[4];
    const float* D  = (const float*)d_in[5];
    const float* Wm = (const float*)d_in[6];
    const float* b  = (const float*)d_in[7];
    float* out = (float*)d_out;

    build_filter_kernel<<<H, TAPS>>>(k0, k1, k2, k3);
    wprep_kernel<<<H * H / 256, 256>>>(Wm);

    conv_mma_fp16<<<BATCH * H, 128>>>(u, D);

    static bool attr_set = false;
    if (!attr_set) {
        cudaFuncSetAttribute(gemm_mma_fp16,
                             cudaFuncAttributeMaxDynamicSharedMemorySize,
                             GEMM_SMEM_BYTES);
        attr_set = true;
    }
    dim3 ggrid(L / GBN, H / GBM, BATCH);
    gemm_mma_fp16<<<ggrid, 128, GEMM_SMEM_BYTES>>>(b, out);
}